// round 15
// baseline (speedup 1.0000x reference)
#include <cuda_runtime.h>
#include <cuda_bf16.h>
#include <cstdint>

#define NN   500000
#define FD   128
#define IN0  144
#define NG   2048
#define EPSV 1e-5f
#define TM   32             // rows per GROUP tile
#define NTH  256
#define APST 73             // packed A stride (b32 units)

// ---- shared memory byte offsets ----
#define F1HI_OFF  0
#define F1LO_OFF  36864
#define F2HI_OFF  73728
#define F2LO_OFF  106496
#define AP_OFF    139264    // + grp*37376 + buf*18688 ; aplo = aphi + 9344B
#define SB_OFF    214016    // + grp*256 + buf*128
#define SMEM_MAIN 214528

#define CH 512              // segsum chunk rows
#define CG 8
#define FDP 132

typedef unsigned long long ull;

// ---------------- scratch ----------------
__device__ __align__(16) float g_z[(size_t)NN * FD];
__device__ __align__(16) float g_xsum[NG * IN0];
__device__ __align__(16) float g_c1[NG * FD];
__device__ __align__(16) float g_c2[NG * FD];
__device__ __align__(16) float g_hsum[NG * FD];
__device__ __align__(16) float g_zsum[NG * FD];
__device__ __align__(16) int   g_start[NG + 1];
__device__ __align__(16) float g_colsum[FD];
__device__ __align__(16) float g_colsq[FD];
__device__ __align__(16) float g_scale[FD];
__device__ __align__(16) float g_shift[FD];

__device__ __forceinline__ uint32_t packbf(float a, float b) {
    uint32_t r;
    asm("cvt.rn.bf16x2.f32 %0, %1, %2;" : "=r"(r) : "f"(b), "f"(a));
    return r;
}
__device__ __forceinline__ float unpk(uint32_t w, int sel) {
    return __uint_as_float(sel ? (w & 0xffff0000u) : (w << 16));
}

#define MMA_B16(acc, a0, a1, a2, a3, b0, b1) \
    asm volatile("mma.sync.aligned.m16n8k16.row.col.f32.bf16.bf16.f32 " \
        "{%0,%1,%2,%3}, {%4,%5,%6,%7}, {%8,%9}, {%0,%1,%2,%3};" \
        : "+f"((acc)[0]), "+f"((acc)[1]), "+f"((acc)[2]), "+f"((acc)[3]) \
        : "r"(a0), "r"(a1), "r"(a2), "r"(a3), "r"(b0), "r"(b1))

#define GBAR(id) asm volatile("bar.sync %0, 128;" :: "r"(id) : "memory")

// ---------------- K_ib: init + segment bounds ----------------
__global__ void k_ib(const int* __restrict__ batch) {
    int i = blockIdx.x * blockDim.x + threadIdx.x;
    if (i < NG * FD) { g_hsum[i] = 0.f; g_zsum[i] = 0.f; }
    if (i < NG * IN0) g_xsum[i] = 0.f;
    if (i < FD) { g_colsum[i] = 0.f; g_colsq[i] = 0.f; }
    if (i < NN) {
        int b = batch[i];
        if (i == 0) {
            for (int g = 0; g <= b; g++) g_start[g] = 0;
        } else {
            int prev = batch[i - 1];
            for (int g = prev + 1; g <= b; g++) g_start[g] = i;
        }
        if (i == NN - 1) {
            for (int g = b + 1; g <= NG; g++) g_start[g] = NN;
        }
    }
}

// ---------------- K1: chunked per-segment column sums (run-length atomics) ----
__global__ void k_segsum(const float* __restrict__ x, const float* __restrict__ pers0,
                         const int* __restrict__ batch) {
    __shared__ int sg[CH];
    int b = blockIdx.x, t = threadIdx.x;
    int s = b * CH;
    int e = min(s + CH, NN);
    int len = e - s;
    for (int i = t; i < len; i += 384) sg[i] = batch[s + i];
    __syncthreads();
    if (t < 256) {
        int c = t & 127;
        int ro = t >> 7;              // 0/1
        float run = 0.f;
        int gc = -1;
        #pragma unroll 4
        for (int i = ro; i < len; i += 2) {
            int g = sg[i];
            if (g != gc) {
                if (gc >= 0) atomicAdd(&g_xsum[gc * IN0 + c], run);
                run = 0.f;
                gc = g;
            }
            run += x[(size_t)(s + i) * FD + c];
        }
        if (gc >= 0) atomicAdd(&g_xsum[gc * IN0 + c], run);
    } else {
        int u = t - 256;              // 0..127
        int c = u & 15;
        int ro = u >> 4;              // 0..7
        int p = c >> 1, comp = c & 1;
        float run = 0.f;
        int gc = -1;
        #pragma unroll 2
        for (int i = ro; i < len; i += 8) {
            int g = sg[i];
            if (g != gc) {
                if (gc >= 0) atomicAdd(&g_xsum[gc * IN0 + 128 + c], run);
                run = 0.f;
                gc = g;
            }
            run += pers0[((size_t)p * NN + (s + i)) * 2 + comp];
        }
        if (gc >= 0) atomicAdd(&g_xsum[gc * IN0 + 128 + c], run);
    }
}

// ---------------- K2/K4: c = gb - (sum/cnt) @ lw^T (+ stat fold WHICH=1) ------
template <int WHICH, int K>
__global__ void k_corr(const float* __restrict__ lw, const float* __restrict__ gb) {
    extern __shared__ float dsm[];
    float* shw = dsm;                  // [K][FDP] transposed
    float* shm = shw + K * FDP;        // [CG][K]
    float* shc = shm + CG * K;         // [CG] inv counts
    float* shn = shc + CG;             // [CG] counts
    const float* msum = WHICH ? g_hsum : g_xsum;
    float* cout       = WHICH ? g_c2   : g_c1;
    int t = threadIdx.x;
    int gbase = blockIdx.x * CG;
    for (int idx = t; idx < FD * K; idx += 256) {
        int j = idx / K;
        int k = idx - j * K;
        shw[k * FDP + j] = lw[idx];
    }
    for (int idx = t; idx < CG * K; idx += 256)
        shm[idx] = msum[gbase * K + idx];
    if (t < CG) {
        int g = gbase + t;
        float cnt = (float)(g_start[g + 1] - g_start[g]);
        shn[t] = cnt;
        shc[t] = 1.f / fmaxf(cnt, 1.f);
    }
    __syncthreads();

    int grp = t >> 7;
    int c = t & 127;
    int g0 = grp * 4;
    float acc[4][4];
    #pragma unroll
    for (int a = 0; a < 4; a++)
        #pragma unroll
        for (int b = 0; b < 4; b++) acc[a][b] = 0.f;

    const float4* m0 = (const float4*)(shm + (g0 + 0) * K);
    const float4* m1 = (const float4*)(shm + (g0 + 1) * K);
    const float4* m2 = (const float4*)(shm + (g0 + 2) * K);
    const float4* m3 = (const float4*)(shm + (g0 + 3) * K);
    #pragma unroll 4
    for (int k4 = 0; k4 < K / 4; k4++) {
        float4 v0 = m0[k4], v1 = m1[k4], v2 = m2[k4], v3 = m3[k4];
        const float* wp = shw + (k4 * 4) * FDP + c;
        float w0 = wp[0], w1 = wp[FDP], w2 = wp[2 * FDP], w3 = wp[3 * FDP];
        acc[0][0] += v0.x * w0; acc[0][1] += v0.y * w1; acc[0][2] += v0.z * w2; acc[0][3] += v0.w * w3;
        acc[1][0] += v1.x * w0; acc[1][1] += v1.y * w1; acc[1][2] += v1.z * w2; acc[1][3] += v1.w * w3;
        acc[2][0] += v2.x * w0; acc[2][1] += v2.y * w1; acc[2][2] += v2.z * w2; acc[2][3] += v2.w * w3;
        acc[3][0] += v3.x * w0; acc[3][1] += v3.y * w1; acc[3][2] += v3.z * w2; acc[3][3] += v3.w * w3;
    }
    float gbv = gb[c];
    float s = 0.f, q = 0.f;
    #pragma unroll
    for (int a = 0; a < 4; a++) {
        int g = gbase + g0 + a;
        float cv = gbv - ((acc[a][0] + acc[a][1]) + (acc[a][2] + acc[a][3])) * shc[g0 + a];
        cout[g * FD + c] = cv;
        if (WHICH) {
            float cnt = shn[g0 + a];
            float zs  = g_zsum[g * FD + c];
            s += cnt * cv;
            q += 2.f * zs * cv + cnt * cv * cv;
        }
    }
    if (WHICH) {
        atomicAdd(&g_colsum[c], s);
        atomicAdd(&g_colsq[c], q);
    }
}

// ---------------- warp GEMM: 16 rows x 64 cols ----------------
template <int KC>
__device__ __forceinline__ void gemm_warp(const uint32_t* __restrict__ aphi,
                                          const uint32_t* __restrict__ aplo,
                                          const ull* __restrict__ fhi,
                                          const ull* __restrict__ flo,
                                          int r0, int ntbase, int lane,
                                          float acc[8][4]) {
    int lr = lane >> 2, lc = lane & 3;
    const uint32_t* h0p = aphi + (r0 + lr) * APST;
    const uint32_t* h1p = h0p + 8 * APST;
    const uint32_t* l0p = aplo + (r0 + lr) * APST;
    const uint32_t* l1p = l0p + 8 * APST;
    #pragma unroll 1
    for (int kc = 0; kc < KC; kc++) {
        int pa = kc * 8 + lc;
        uint32_t a0h = h0p[pa], a1h = h1p[pa], a2h = h0p[pa + 4], a3h = h1p[pa + 4];
        uint32_t a0l = l0p[pa], a1l = l1p[pa], a2l = l0p[pa + 4], a3l = l1p[pa + 4];
        #pragma unroll
        for (int nt = 0; nt < 8; nt++) {
            ull bh = fhi[(kc * 16 + ntbase + nt) * 32 + lane];
            ull bl = flo[(kc * 16 + ntbase + nt) * 32 + lane];
            uint32_t b0h = (uint32_t)bh, b1h = (uint32_t)(bh >> 32);
            uint32_t b0l = (uint32_t)bl, b1l = (uint32_t)(bl >> 32);
            MMA_B16(acc[nt], a0h, a1h, a2h, a3h, b0h, b1h);
            MMA_B16(acc[nt], a0h, a1h, a2h, a3h, b0l, b1l);
            MMA_B16(acc[nt], a0l, a1l, a2l, a3l, b0h, b1h);
        }
    }
}

// ---------------- K3: persistent fused main, 2 pipelines x double-buffered ----
__global__ __launch_bounds__(NTH, 1)
void k_main(const float* __restrict__ x, const int* __restrict__ batch,
            const float* __restrict__ pers0,
            const float* __restrict__ g1w, const float* __restrict__ g2w) {
    extern __shared__ char sal[];
    ull* f1hi = (ull*)(sal + F1HI_OFF);
    ull* f1lo = (ull*)(sal + F1LO_OFF);
    ull* f2hi = (ull*)(sal + F2HI_OFF);
    ull* f2lo = (ull*)(sal + F2LO_OFF);

    int t = threadIdx.x;
    int grp = t >> 7;
    int gt = t & 127;
    int w2 = gt >> 5, lane = gt & 31;
    int r0 = (w2 >> 1) * 16;
    int h0 = (w2 & 1) * 64;
    int ntbase = h0 >> 3;
    int lr = lane >> 2, lc = lane & 3;
    int barid = 1 + grp;

    // ---- one-time: B fragments ----
    for (int idx = t; idx < 9 * 16 * 32; idx += NTH) {
        int kc = idx >> 9, rem = idx & 511;
        int nt = rem >> 5, l = rem & 31;
        int n = nt * 8 + (l >> 2);
        int k0 = kc * 16 + ((l & 3) << 1);
        const float* wr = g1w + n * IN0;
        float w00 = wr[k0], w01 = wr[k0 + 1], w10 = wr[k0 + 8], w11 = wr[k0 + 9];
        uint32_t u0 = packbf(w00, w01), u1 = packbf(w10, w11);
        f1hi[idx] = (ull)u0 | ((ull)u1 << 32);
        float r00 = w00 - unpk(u0, 0), r01 = w01 - unpk(u0, 1);
        float r10 = w10 - unpk(u1, 0), r11 = w11 - unpk(u1, 1);
        uint32_t v0 = packbf(r00, r01), v1 = packbf(r10, r11);
        f1lo[idx] = (ull)v0 | ((ull)v1 << 32);
    }
    for (int idx = t; idx < 8 * 16 * 32; idx += NTH) {
        int kc = idx >> 9, rem = idx & 511;
        int nt = rem >> 5, l = rem & 31;
        int n = nt * 8 + (l >> 2);
        int k0 = kc * 16 + ((l & 3) << 1);
        const float* wr = g2w + n * FD;
        float w00 = wr[k0], w01 = wr[k0 + 1], w10 = wr[k0 + 8], w11 = wr[k0 + 9];
        uint32_t u0 = packbf(w00, w01), u1 = packbf(w10, w11);
        f2hi[idx] = (ull)u0 | ((ull)u1 << 32);
        float r00 = w00 - unpk(u0, 0), r01 = w01 - unpk(u0, 1);
        float r10 = w10 - unpk(u1, 0), r11 = w11 - unpk(u1, 1);
        uint32_t v0 = packbf(r00, r01), v1 = packbf(r10, r11);
        f2lo[idx] = (ull)v0 | ((ull)v1 << 32);
    }
    __syncthreads();

    int c = gt;                       // scan/stat column (0..127)
    int sel = c & 1;
    int pcw = c >> 1;
    float csum = 0.f, csq = 0.f;
    float acc[8][4];
    const int NT = NN / TM;           // 15625
    const int STEP = gridDim.x * 2;
    const float2* pers2 = (const float2*)pers0;

    // ---- prefetch regs ----
    float4 nx[8];
    float2 np[2];
    int nb = -1;
    float2 c1a[8], c1b[8];

    int tile0 = blockIdx.x * 2 + grp;
    if (tile0 < NT) {
        int n0 = tile0 * TM;
        #pragma unroll
        for (int j = 0; j < 8; j++) {
            int idx = gt + j * 128;
            int r = idx >> 5, q = idx & 31;
            nx[j] = *(const float4*)(x + (size_t)(n0 + r) * FD + q * 4);
        }
        #pragma unroll
        for (int j = 0; j < 2; j++) {
            int idx = gt + j * 128;
            int r = idx & 31, p = idx >> 5;
            np[j] = pers2[(size_t)p * NN + (n0 + r)];
        }
        if (gt < TM) nb = batch[n0 + gt];
    }

    int par = 0;
    for (int tile = tile0; tile < NT; tile += STEP) {
        int n0 = tile * TM;
        uint32_t* aphi = (uint32_t*)(sal + AP_OFF + grp * 37376 + par * 18688);
        uint32_t* aplo = aphi + 9344 / 4;
        int* sb = (int*)(sal + SB_OFF + grp * 256 + par * 128);
        par ^= 1;

        // ---- convert prefetched tile -> packed A1 (buf par) ----
        #pragma unroll
        for (int j = 0; j < 8; j++) {
            int idx = gt + j * 128;
            int r = idx >> 5, q = idx & 31;
            float4 v = nx[j];
            uint32_t u0 = packbf(v.x, v.y);
            uint32_t u1 = packbf(v.z, v.w);
            aphi[r * APST + 2 * q]     = u0;
            aphi[r * APST + 2 * q + 1] = u1;
            aplo[r * APST + 2 * q]     = packbf(v.x - unpk(u0, 0), v.y - unpk(u0, 1));
            aplo[r * APST + 2 * q + 1] = packbf(v.z - unpk(u1, 0), v.w - unpk(u1, 1));
        }
        #pragma unroll
        for (int j = 0; j < 2; j++) {
            int idx = gt + j * 128;
            int r = idx & 31, p = idx >> 5;
            float2 v = np[j];
            uint32_t hp = packbf(v.x, v.y);
            aphi[r * APST + 64 + p] = hp;
            aplo[r * APST + 64 + p] = packbf(v.x - unpk(hp, 0), v.y - unpk(hp, 1));
        }
        if (gt < TM) sb[gt] = nb;
        GBAR(barid);   // (B) A1 + sb ready (also orders prev zsum of this buf)

        // ---- prefetch c1 corrections ----
        {
            int ra = r0 + lr, rb = ra + 8;
            int ga = sb[ra], gb_ = sb[rb];
            #pragma unroll
            for (int nt = 0; nt < 8; nt++) {
                int ncol = h0 + nt * 8 + 2 * lc;
                c1a[nt] = (ga >= 0) ? *(const float2*)(g_c1 + ga * FD + ncol)
                                    : make_float2(0.f, 0.f);
                c1b[nt] = (gb_ >= 0) ? *(const float2*)(g_c1 + gb_ * FD + ncol)
                                     : make_float2(0.f, 0.f);
            }
        }

        // ---- issue next-tile prefetch (hidden behind GEMMs) ----
        {
            int tn = tile + STEP;
            if (tn < NT) {
                int m0 = tn * TM;
                #pragma unroll
                for (int j = 0; j < 8; j++) {
                    int idx = gt + j * 128;
                    int r = idx >> 5, q = idx & 31;
                    nx[j] = *(const float4*)(x + (size_t)(m0 + r) * FD + q * 4);
                }
                #pragma unroll
                for (int j = 0; j < 2; j++) {
                    int idx = gt + j * 128;
                    int r = idx & 31, p = idx >> 5;
                    np[j] = pers2[(size_t)p * NN + (m0 + r)];
                }
                if (gt < TM) nb = batch[m0 + gt];
            }
        }

        // ---- GEMM1 ----
        #pragma unroll
        for (int nt = 0; nt < 8; nt++)
            #pragma unroll
            for (int q = 0; q < 4; q++) acc[nt][q] = 0.f;
        gemm_warp<9>(aphi, aplo, f1hi, f1lo, r0, ntbase, lane, acc);
        GBAR(barid);   // (C) A1 reads done (epi1 overwrites words 0..63)

        // ---- epilogue 1: h = relu(acc + c1) -> packed A2 ----
        {
            int ra = r0 + lr, rb = ra + 8;
            #pragma unroll
            for (int nt = 0; nt < 8; nt++) {
                int ncol = h0 + nt * 8 + 2 * lc;
                int pc = (ncol >> 1);
                float ha0 = fmaxf(acc[nt][0] + c1a[nt].x, 0.f);
                float ha1 = fmaxf(acc[nt][1] + c1a[nt].y, 0.f);
                float hb0 = fmaxf(acc[nt][2] + c1b[nt].x, 0.f);
                float hb1 = fmaxf(acc[nt][3] + c1b[nt].y, 0.f);
                uint32_t hpa = packbf(ha0, ha1);
                aphi[ra * APST + pc] = hpa;
                aplo[ra * APST + pc] = packbf(ha0 - unpk(hpa, 0), ha1 - unpk(hpa, 1));
                uint32_t hpb = packbf(hb0, hb1);
                aphi[rb * APST + pc] = hpb;
                aplo[rb * APST + pc] = packbf(hb0 - unpk(hpb, 0), hb1 - unpk(hpb, 1));
            }
        }
        GBAR(barid);   // (D) A2 (= packed h) ready

        // ---- GEMM2 ----
        #pragma unroll
        for (int nt = 0; nt < 8; nt++)
            #pragma unroll
            for (int q = 0; q < 4; q++) acc[nt][q] = 0.f;
        gemm_warp<8>(aphi, aplo, f2hi, f2lo, r0, ntbase, lane, acc);

        // ---- hsum (reads packed h; overlaps in-flight MMAs) ----
        {
            float run = 0.f;
            int gc = -1;
            for (int r = 0; r < TM; r++) {
                int g = sb[r];
                if (g != gc) {
                    if (gc >= 0) atomicAdd(&g_hsum[gc * FD + c], run);
                    run = 0.f;
                    gc = g;
                }
                if (g >= 0)
                    run += unpk(aphi[r * APST + pcw], sel) + unpk(aplo[r * APST + pcw], sel);
            }
            if (gc >= 0) atomicAdd(&g_hsum[gc * FD + c], run);
        }
        GBAR(barid);   // (E) GEMM2 + hsum reads done (epi2 overwrites words 0..63)

        // ---- epilogue 2: z -> gmem (fp32) + packed z -> buf ----
        {
            int ra = r0 + lr, rb = ra + 8;
            #pragma unroll
            for (int nt = 0; nt < 8; nt++) {
                int ncol = h0 + nt * 8 + 2 * lc;
                int pc = (ncol >> 1);
                float za0 = acc[nt][0], za1 = acc[nt][1];
                float zb0 = acc[nt][2], zb1 = acc[nt][3];
                *(float2*)(g_z + (size_t)(n0 + ra) * FD + ncol) = make_float2(za0, za1);
                *(float2*)(g_z + (size_t)(n0 + rb) * FD + ncol) = make_float2(zb0, zb1);
                uint32_t ua = packbf(za0, za1);
                aphi[ra * APST + pc] = ua;
                aplo[ra * APST + pc] = packbf(za0 - unpk(ua, 0), za1 - unpk(ua, 1));
                uint32_t ub = packbf(zb0, zb1);
                aphi[rb * APST + pc] = ub;
                aplo[rb * APST + pc] = packbf(zb0 - unpk(ub, 0), zb1 - unpk(ub, 1));
            }
        }
        GBAR(barid);   // (F) packed z ready

        // ---- zsum + column stats (reads packed z) ----
        {
            float run = 0.f;
            int gc = -1;
            for (int r = 0; r < TM; r++) {
                int g = sb[r];
                if (g != gc) {
                    if (gc >= 0) atomicAdd(&g_zsum[gc * FD + c], run);
                    run = 0.f;
                    gc = g;
                }
                if (g >= 0) {
                    float v = unpk(aphi[r * APST + pcw], sel) + unpk(aplo[r * APST + pcw], sel);
                    run += v;
                    csum += v;
                    csq += v * v;
                }
            }
            if (gc >= 0) atomicAdd(&g_zsum[gc * FD + c], run);
        }
        // no trailing barrier: next iteration uses the other buffer;
        // its (B) barrier orders this zsum before this buffer's reuse.
    }

    atomicAdd(&g_colsum[c], csum);
    atomicAdd(&g_colsq[c], csq);
}

__global__ void k_fin(const float* __restrict__ bng, const float* __restrict__ bnb) {
    int c = threadIdx.x;
    float mu  = g_colsum[c] / (float)NN;
    float var = g_colsq[c] / (float)NN - mu * mu;
    float inv = rsqrtf(var + EPSV);
    float sc  = bng[c] * inv;
    g_scale[c] = sc;
    g_shift[c] = bnb[c] - mu * sc;
}

__global__ void k_out(const float* __restrict__ x, const int* __restrict__ batch,
                      float* __restrict__ out) {
    int idx = blockIdx.x * blockDim.x + threadIdx.x;
    if (idx >= NN * 32) return;
    int n = idx >> 5;
    int qd = idx & 31;
    int c0 = qd << 2;
    int g = batch[n];
    float4 zvv = *(const float4*)(g_z + (size_t)n * FD + c0);
    float4 xv = *(const float4*)(x + (size_t)n * FD + c0);
    float4 cv = *(const float4*)(g_c2 + g * FD + c0);
    float4 sc = *(const float4*)(g_scale + c0);
    float4 sh = *(const float4*)(g_shift + c0);
    float4 o;
    o.x = xv.x + (zvv.x + cv.x) * sc.x + sh.x;
    o.y = xv.y + (zvv.y + cv.y) * sc.y + sh.y;
    o.z = xv.z + (zvv.z + cv.z) * sc.z + sh.z;
    o.w = xv.w + (zvv.w + cv.w) * sc.w + sh.w;
    ((float4*)out)[idx] = o;
}

// ---------------- host ----------------
extern "C" void kernel_launch(void* const* d_in, const int* in_sizes, int n_in,
                              void* d_out, int out_size) {
    const float* x     = (const float*)d_in[0];
    const int*   batch = (const int*)d_in[1];
    const float* pers0 = (const float*)d_in[2];
    const float* g1w   = (const float*)d_in[3];
    const float* g1b   = (const float*)d_in[4];
    const float* l1w   = (const float*)d_in[5];
    const float* g2w   = (const float*)d_in[6];
    const float* g2b   = (const float*)d_in[7];
    const float* l2w   = (const float*)d_in[8];
    const float* bng   = (const float*)d_in[9];
    const float* bnb   = (const float*)d_in[10];
    float* out = (float*)d_out;

    int sms = 148;
    cudaDeviceGetAttribute(&sms, cudaDevAttrMultiProcessorCount, 0);

    const int smem_corr1 = (IN0 * FDP + CG * IN0 + 2 * CG) * 4;
    const int smem_corr2 = (FD * FDP + CG * FD + 2 * CG) * 4;
    cudaFuncSetAttribute(k_main, cudaFuncAttributeMaxDynamicSharedMemorySize, SMEM_MAIN);
    cudaFuncSetAttribute(k_corr<0, IN0>, cudaFuncAttributeMaxDynamicSharedMemorySize, smem_corr1);
    cudaFuncSetAttribute(k_corr<1, FD>,  cudaFuncAttributeMaxDynamicSharedMemorySize, smem_corr2);

    k_ib<<<(NN + 255) / 256, 256>>>(batch);                        // 1
    k_segsum<<<(NN + CH - 1) / CH, 384>>>(x, pers0, batch);        // 2
    k_corr<0, IN0><<<NG / CG, 256, smem_corr1>>>(l1w, g1b);        // 3
    k_main<<<sms, NTH, SMEM_MAIN>>>(x, batch, pers0, g1w, g2w);    // 4
    k_corr<1, FD><<<NG / CG, 256, smem_corr2>>>(l2w, g2b);         // 5
    k_fin<<<1, 128>>>(bng, bnb);                                   // 6
    k_out<<<(NN * 32 + 255) / 256, 256>>>(x, batch, out);          // 7
}